// round 2
// baseline (speedup 1.0000x reference)
#include <cuda_runtime.h>
#include <cstdint>

// Problem constants: B=2, N=256, D=128
namespace {
constexpr int Bc = 2;
constexpr int Nc = 256;
constexpr int Dc = 128;
constexpr int MROWS = Bc * Nc * Nc;            // 131072 rows of structure_matrix
constexpr float SCALE = 0.08838834764831845f;  // 1/sqrt(128)
constexpr float LNEPS = 1e-5f;
}

// Scratch (allocation-free rule: __device__ globals). 274 MB total.
__device__ float g_q[MROWS * Dc];         // 64 MB
__device__ float g_k[MROWS * Dc];         // 64 MB
__device__ float g_v[MROWS * Dc];         // 64 MB
__device__ float g_ctx[MROWS * Dc];       // 64 MB

// ---------------------------------------------------------------------------
// Kernel A: fused QKV projection.  out[m,:] = S[m,:] @ W + b  for W in {Wq,Wk,Wv}
// Tile: BM=64, BN=128, BK=32.  256 thr, 4x8 accum per thread.
// ---------------------------------------------------------------------------
__global__ __launch_bounds__(256) void qkv_kernel(
    const float* __restrict__ S,
    const float* __restrict__ Wq, const float* __restrict__ bq,
    const float* __restrict__ Wk, const float* __restrict__ bk,
    const float* __restrict__ Wv, const float* __restrict__ bv)
{
    __shared__ float Ss[64][33];   // padded: conflict-free reads
    __shared__ float Ws[32][128];

    const float *W, *bias;
    float* out;
    if (blockIdx.y == 0)      { W = Wq; bias = bq; out = g_q; }
    else if (blockIdx.y == 1) { W = Wk; bias = bk; out = g_k; }
    else                      { W = Wv; bias = bv; out = g_v; }

    const int m0   = blockIdx.x * 64;
    const int t    = threadIdx.x;
    const int w    = t >> 5, lane = t & 31;
    const int mb   = (w >> 1) * 16 + (lane >> 3) * 4;   // 0..60
    const int nb   = (w & 1) * 64 + (lane & 7) * 8;     // 0..120

    float acc[4][8];
#pragma unroll
    for (int i = 0; i < 4; i++)
#pragma unroll
        for (int j = 0; j < 8; j++) acc[i][j] = 0.f;

    const int lr = t >> 3;          // 0..31
    const int lc = (t & 7) * 4;     // 0..28
    const int wr = t >> 5;          // 0..7
    const int wc = (t & 31) * 4;    // 0..124

    for (int k0 = 0; k0 < 128; k0 += 32) {
#pragma unroll
        for (int rr = 0; rr < 64; rr += 32) {
            float4 v = *reinterpret_cast<const float4*>(
                S + (size_t)(m0 + lr + rr) * Dc + k0 + lc);
            Ss[lr + rr][lc + 0] = v.x; Ss[lr + rr][lc + 1] = v.y;
            Ss[lr + rr][lc + 2] = v.z; Ss[lr + rr][lc + 3] = v.w;
        }
#pragma unroll
        for (int rr = 0; rr < 32; rr += 8) {
            *reinterpret_cast<float4*>(&Ws[wr + rr][wc]) =
                *reinterpret_cast<const float4*>(W + (size_t)(k0 + wr + rr) * Dc + wc);
        }
        __syncthreads();
#pragma unroll
        for (int kk = 0; kk < 32; kk++) {
            float a[4], b[8];
#pragma unroll
            for (int i = 0; i < 4; i++) a[i] = Ss[mb + i][kk];
            float4 b0 = *reinterpret_cast<const float4*>(&Ws[kk][nb]);
            float4 b1 = *reinterpret_cast<const float4*>(&Ws[kk][nb + 4]);
            b[0] = b0.x; b[1] = b0.y; b[2] = b0.z; b[3] = b0.w;
            b[4] = b1.x; b[5] = b1.y; b[6] = b1.z; b[7] = b1.w;
#pragma unroll
            for (int i = 0; i < 4; i++)
#pragma unroll
                for (int j = 0; j < 8; j++) acc[i][j] = fmaf(a[i], b[j], acc[i][j]);
        }
        __syncthreads();
    }

    float bv8[8];
#pragma unroll
    for (int j = 0; j < 8; j++) bv8[j] = __ldg(bias + nb + j);
#pragma unroll
    for (int i = 0; i < 4; i++) {
        float4 o0 = make_float4(acc[i][0] + bv8[0], acc[i][1] + bv8[1],
                                acc[i][2] + bv8[2], acc[i][3] + bv8[3]);
        float4 o1 = make_float4(acc[i][4] + bv8[4], acc[i][5] + bv8[5],
                                acc[i][6] + bv8[6], acc[i][7] + bv8[7]);
        size_t off = (size_t)(m0 + mb + i) * Dc + nb;
        *reinterpret_cast<float4*>(out + off)     = o0;
        *reinterpret_cast<float4*>(out + off + 4) = o1;
    }
}

// ---------------------------------------------------------------------------
// Kernel B (fused attention): per (b,i), j-tile of 64 rows:
//   ctx[j,:] = sum_k relu(scale * K[j,:].Q[k,:]) * V[k,:]
// k processed in tiles of 64:
//   stage 1: S_tile[64j][64k] = relu(scale * K_tile Q_tile^T)  -> smem
//   stage 2: ctx_acc[64j][128d] += S_tile @ V_tile
// Never materializes scores in HBM (removes 256 MB of traffic vs unfused).
// ---------------------------------------------------------------------------
__global__ __launch_bounds__(256) void attn_kernel()
{
    __shared__ float Ks[64][33];    // K tile  [j][d-chunk]
    __shared__ float Qt[32][68];    // Q tile transposed [d-chunk][k]
    __shared__ float Ss[64][68];    // relu'd scores [j][k]  (pad 68: float4-ok)
    __shared__ float Vs[16][128];   // V chunk [k-sub][d]

    const int bi = blockIdx.y;
    const int j0 = blockIdx.x * 64;
    const float* Qp = g_q   + (size_t)bi * Nc * Dc;
    const float* Kp = g_k   + (size_t)bi * Nc * Dc;
    const float* Vp = g_v   + (size_t)bi * Nc * Dc;
    float*       Cp = g_ctx + (size_t)bi * Nc * Dc;

    const int t = threadIdx.x;
    const int w = t >> 5, lane = t & 31;
    // stage-1 mapping: 4x4 over [64j x 64k]
    const int mb1 = (w >> 1) * 16 + (lane >> 3) * 4;   // j   0..60
    const int nb1 = (w & 1) * 32 + (lane & 7) * 4;     // k   0..60
    // stage-2 mapping: 4x8 over [64j x 128d]
    const int nb2 = (w & 1) * 64 + (lane & 7) * 8;     // d   0..120

    const int lr = t >> 3;          // 0..31
    const int lc = (t & 7) * 4;     // 0..28
    const int vr = t >> 4;          // 0..15
    const int vc = (t & 15) * 8;    // 0..120

    float ctx[4][8];
#pragma unroll
    for (int i = 0; i < 4; i++)
#pragma unroll
        for (int j = 0; j < 8; j++) ctx[i][j] = 0.f;

    for (int k0 = 0; k0 < Nc; k0 += 64) {
        // ---- stage 1: S = relu(scale * K_j Q_k^T), 64x64x128 NT GEMM ----
        float sacc[4][4];
#pragma unroll
        for (int i = 0; i < 4; i++)
#pragma unroll
            for (int j = 0; j < 4; j++) sacc[i][j] = 0.f;

        for (int d0 = 0; d0 < Dc; d0 += 32) {
#pragma unroll
            for (int rr = 0; rr < 64; rr += 32) {
                float4 kv = *reinterpret_cast<const float4*>(
                    Kp + (size_t)(j0 + lr + rr) * Dc + d0 + lc);
                Ks[lr + rr][lc + 0] = kv.x; Ks[lr + rr][lc + 1] = kv.y;
                Ks[lr + rr][lc + 2] = kv.z; Ks[lr + rr][lc + 3] = kv.w;
                float4 qv = *reinterpret_cast<const float4*>(
                    Qp + (size_t)(k0 + lr + rr) * Dc + d0 + lc);
                Qt[lc + 0][lr + rr] = qv.x; Qt[lc + 1][lr + rr] = qv.y;
                Qt[lc + 2][lr + rr] = qv.z; Qt[lc + 3][lr + rr] = qv.w;
            }
            __syncthreads();
#pragma unroll
            for (int dd = 0; dd < 32; dd++) {
                float a[4];
#pragma unroll
                for (int i = 0; i < 4; i++) a[i] = Ks[mb1 + i][dd];
                float4 b4 = *reinterpret_cast<const float4*>(&Qt[dd][nb1]);
#pragma unroll
                for (int i = 0; i < 4; i++) {
                    sacc[i][0] = fmaf(a[i], b4.x, sacc[i][0]);
                    sacc[i][1] = fmaf(a[i], b4.y, sacc[i][1]);
                    sacc[i][2] = fmaf(a[i], b4.z, sacc[i][2]);
                    sacc[i][3] = fmaf(a[i], b4.w, sacc[i][3]);
                }
            }
            __syncthreads();
        }

        // relu + scale -> Ss
#pragma unroll
        for (int i = 0; i < 4; i++) {
            float4 o;
            o.x = fmaxf(sacc[i][0] * SCALE, 0.f);
            o.y = fmaxf(sacc[i][1] * SCALE, 0.f);
            o.z = fmaxf(sacc[i][2] * SCALE, 0.f);
            o.w = fmaxf(sacc[i][3] * SCALE, 0.f);
            *reinterpret_cast<float4*>(&Ss[mb1 + i][nb1]) = o;
        }
        __syncthreads();

        // ---- stage 2: ctx += Ss[64x64] @ V[k0:k0+64, 0:128] ----
        for (int kk0 = 0; kk0 < 64; kk0 += 16) {
            *reinterpret_cast<float4*>(&Vs[vr][vc]) =
                *reinterpret_cast<const float4*>(Vp + (size_t)(k0 + kk0 + vr) * Dc + vc);
            *reinterpret_cast<float4*>(&Vs[vr][vc + 4]) =
                *reinterpret_cast<const float4*>(Vp + (size_t)(k0 + kk0 + vr) * Dc + vc + 4);
            __syncthreads();
#pragma unroll
            for (int kk = 0; kk < 16; kk++) {
                float a[4], b[8];
#pragma unroll
                for (int i = 0; i < 4; i++) a[i] = Ss[mb1 + i][kk0 + kk];
                float4 b0 = *reinterpret_cast<const float4*>(&Vs[kk][nb2]);
                float4 b1 = *reinterpret_cast<const float4*>(&Vs[kk][nb2 + 4]);
                b[0] = b0.x; b[1] = b0.y; b[2] = b0.z; b[3] = b0.w;
                b[4] = b1.x; b[5] = b1.y; b[6] = b1.z; b[7] = b1.w;
#pragma unroll
                for (int i = 0; i < 4; i++)
#pragma unroll
                    for (int j = 0; j < 8; j++) ctx[i][j] = fmaf(a[i], b[j], ctx[i][j]);
            }
            __syncthreads();
        }
        // last sync above also guards Ss/Ks/Qt overwrite in next k0 iteration
    }

#pragma unroll
    for (int i = 0; i < 4; i++) {
        size_t off = (size_t)(j0 + mb1 + i) * Dc + nb2;
        *reinterpret_cast<float4*>(Cp + off) =
            make_float4(ctx[i][0], ctx[i][1], ctx[i][2], ctx[i][3]);
        *reinterpret_cast<float4*>(Cp + off + 4) =
            make_float4(ctx[i][4], ctx[i][5], ctx[i][6], ctx[i][7]);
    }
}

// ---------------------------------------------------------------------------
// Kernel C: out = LN( ctx @ Wo + bo + S ).  GEMM, then fused LayerNorm.
// ---------------------------------------------------------------------------
__global__ __launch_bounds__(256) void out_ln_kernel(
    const float* __restrict__ Sres,
    const float* __restrict__ Wo, const float* __restrict__ bo,
    const float* __restrict__ lng, const float* __restrict__ lnb,
    float* __restrict__ out)
{
    __shared__ float smemraw[64 * 132];   // 33 KB, reused across phases
    float (*Ss)[33]  = reinterpret_cast<float(*)[33]>(smemraw);
    float (*Ws)[128] = reinterpret_cast<float(*)[128]>(smemraw + 64 * 33);
    float (*Xs)[132] = reinterpret_cast<float(*)[132]>(smemraw);

    const int m0 = blockIdx.x * 64;
    const int t  = threadIdx.x;
    const int w  = t >> 5, lane = t & 31;
    const int mb = (w >> 1) * 16 + (lane >> 3) * 4;
    const int nb = (w & 1) * 64 + (lane & 7) * 8;

    float acc[4][8];
#pragma unroll
    for (int i = 0; i < 4; i++)
#pragma unroll
        for (int j = 0; j < 8; j++) acc[i][j] = 0.f;

    const int lr = t >> 3;
    const int lc = (t & 7) * 4;
    const int wr = t >> 5;
    const int wc = (t & 31) * 4;

    for (int k0 = 0; k0 < 128; k0 += 32) {
#pragma unroll
        for (int rr = 0; rr < 64; rr += 32) {
            float4 v = *reinterpret_cast<const float4*>(
                g_ctx + (size_t)(m0 + lr + rr) * Dc + k0 + lc);
            Ss[lr + rr][lc + 0] = v.x; Ss[lr + rr][lc + 1] = v.y;
            Ss[lr + rr][lc + 2] = v.z; Ss[lr + rr][lc + 3] = v.w;
        }
#pragma unroll
        for (int rr = 0; rr < 32; rr += 8) {
            *reinterpret_cast<float4*>(&Ws[wr + rr][wc]) =
                *reinterpret_cast<const float4*>(Wo + (size_t)(k0 + wr + rr) * Dc + wc);
        }
        __syncthreads();
#pragma unroll
        for (int kk = 0; kk < 32; kk++) {
            float a[4], b[8];
#pragma unroll
            for (int i = 0; i < 4; i++) a[i] = Ss[mb + i][kk];
            float4 b0 = *reinterpret_cast<const float4*>(&Ws[kk][nb]);
            float4 b1 = *reinterpret_cast<const float4*>(&Ws[kk][nb + 4]);
            b[0] = b0.x; b[1] = b0.y; b[2] = b0.z; b[3] = b0.w;
            b[4] = b1.x; b[5] = b1.y; b[6] = b1.z; b[7] = b1.w;
#pragma unroll
            for (int i = 0; i < 4; i++)
#pragma unroll
                for (int j = 0; j < 8; j++) acc[i][j] = fmaf(a[i], b[j], acc[i][j]);
        }
        __syncthreads();   // last sync also guards the Ss/Ws -> Xs aliasing below
    }

    // x = gemm + bias + residual, staged to smem for the row reduction
#pragma unroll
    for (int i = 0; i < 4; i++) {
        size_t roff = (size_t)(m0 + mb + i) * Dc + nb;
#pragma unroll
        for (int j = 0; j < 8; j += 4) {
            float4 r = *reinterpret_cast<const float4*>(Sres + roff + j);
            Xs[mb + i][nb + j + 0] = acc[i][j + 0] + __ldg(bo + nb + j + 0) + r.x;
            Xs[mb + i][nb + j + 1] = acc[i][j + 1] + __ldg(bo + nb + j + 1) + r.y;
            Xs[mb + i][nb + j + 2] = acc[i][j + 2] + __ldg(bo + nb + j + 2) + r.z;
            Xs[mb + i][nb + j + 3] = acc[i][j + 3] + __ldg(bo + nb + j + 3) + r.w;
        }
    }
    __syncthreads();

    // LayerNorm: 4 threads per row (row = t/4), 32 cols each, shuffle-combine
    const int row  = t >> 2;
    const int part = (t & 3) * 32;
    float sum = 0.f, sq = 0.f;
#pragma unroll
    for (int c = 0; c < 32; c++) {
        float x = Xs[row][part + c];
        sum += x; sq += x * x;
    }
    sum += __shfl_xor_sync(0xffffffffu, sum, 1);
    sq  += __shfl_xor_sync(0xffffffffu, sq, 1);
    sum += __shfl_xor_sync(0xffffffffu, sum, 2);
    sq  += __shfl_xor_sync(0xffffffffu, sq, 2);
    const float mean = sum * (1.f / 128.f);
    const float var  = sq * (1.f / 128.f) - mean * mean;
    const float inv  = rsqrtf(var + LNEPS);

#pragma unroll
    for (int c = 0; c < 32; c += 4) {
        float4 o;
        o.x = (Xs[row][part + c + 0] - mean) * inv * __ldg(lng + part + c + 0) + __ldg(lnb + part + c + 0);
        o.y = (Xs[row][part + c + 1] - mean) * inv * __ldg(lng + part + c + 1) + __ldg(lnb + part + c + 1);
        o.z = (Xs[row][part + c + 2] - mean) * inv * __ldg(lng + part + c + 2) + __ldg(lnb + part + c + 2);
        o.w = (Xs[row][part + c + 3] - mean) * inv * __ldg(lng + part + c + 3) + __ldg(lnb + part + c + 3);
        *reinterpret_cast<float4*>(out + (size_t)(m0 + row) * Dc + part + c) = o;
    }
}

// ---------------------------------------------------------------------------
// Launch.  Input order (metadata): hidden_states, structure_matrix, Wq, bq,
// Wk, bk, Wv, bv, Wo, bo, ln_g, ln_b.  hidden_states is unused by reference.
// ---------------------------------------------------------------------------
extern "C" void kernel_launch(void* const* d_in, const int* in_sizes, int n_in,
                              void* d_out, int out_size)
{
    const float* S   = (const float*)d_in[1];
    const float* Wq  = (const float*)d_in[2];
    const float* bq  = (const float*)d_in[3];
    const float* Wk  = (const float*)d_in[4];
    const float* bk  = (const float*)d_in[5];
    const float* Wv  = (const float*)d_in[6];
    const float* bv  = (const float*)d_in[7];
    const float* Wo  = (const float*)d_in[8];
    const float* bo  = (const float*)d_in[9];
    const float* lng = (const float*)d_in[10];
    const float* lnb = (const float*)d_in[11];
    float* out = (float*)d_out;

    qkv_kernel<<<dim3(MROWS / 64, 3), 256>>>(S, Wq, bq, Wk, bk, Wv, bv);
    attn_kernel<<<dim3(Nc / 64, Bc * Nc), 256>>>();
    out_ln_kernel<<<MROWS / 64, 256>>>(S, Wo, bo, lng, lnb, out);
}

// round 6
// speedup vs baseline: 1.8213x; 1.8213x over previous
#include <cuda_runtime.h>
#include <cuda_bf16.h>
#include <cstdint>

// Problem constants: B=2, N=256, D=128
namespace {
constexpr int Bc = 2;
constexpr int Nc = 256;
constexpr int Dc = 128;
constexpr int MROWS = Bc * Nc * Nc;            // 131072
constexpr float SCALE = 0.08838834764831845f;  // 1/sqrt(128)
constexpr float LNEPS = 1e-5f;
}

// Scratch (__device__ globals; 256 MB total).
// q/k/v stored as bf16x2-packed planes: word w at [row][c] holds bf16 of cols 2c (low) and 2c+1 (high).
__device__ uint32_t g_qhi[MROWS * 64];
__device__ uint32_t g_qlo[MROWS * 64];
__device__ uint32_t g_khi[MROWS * 64];
__device__ uint32_t g_klo[MROWS * 64];
__device__ uint32_t g_vhi[MROWS * 64];
__device__ uint32_t g_vlo[MROWS * 64];
__device__ float    g_ctx[MROWS * Dc];

// ===========================================================================
// Helpers: mma.sync bf16, ldmatrix, prmt, swizzled smem offsets, fp32 split
// ===========================================================================
__device__ __forceinline__ uint32_t smem_u32(const void* p) {
    uint32_t a;
    asm("{ .reg .u64 t; cvta.to.shared.u64 t, %1; cvt.u32.u64 %0, t; }"
        : "=r"(a) : "l"(p));
    return a;
}

__device__ __forceinline__ void mma_bf16(float* c, const uint32_t* a, const uint32_t* b) {
    asm volatile("mma.sync.aligned.m16n8k16.row.col.f32.bf16.bf16.f32 "
                 "{%0,%1,%2,%3}, {%4,%5,%6,%7}, {%8,%9}, {%0,%1,%2,%3};"
                 : "+f"(c[0]), "+f"(c[1]), "+f"(c[2]), "+f"(c[3])
                 : "r"(a[0]), "r"(a[1]), "r"(a[2]), "r"(a[3]), "r"(b[0]), "r"(b[1]));
}

__device__ __forceinline__ void ldm_x4(uint32_t* r, uint32_t addr) {
    asm volatile("ldmatrix.sync.aligned.m8n8.x4.shared.b16 {%0,%1,%2,%3}, [%4];"
                 : "=r"(r[0]), "=r"(r[1]), "=r"(r[2]), "=r"(r[3]) : "r"(addr));
}
__device__ __forceinline__ void ldm_x2(uint32_t* r, uint32_t addr) {
    asm volatile("ldmatrix.sync.aligned.m8n8.x2.shared.b16 {%0,%1}, [%2];"
                 : "=r"(r[0]), "=r"(r[1]) : "r"(addr));
}
__device__ __forceinline__ uint32_t prmt(uint32_t a, uint32_t b, uint32_t sel) {
    uint32_t d;
    asm("prmt.b32 %0, %1, %2, %3;" : "=r"(d) : "r"(a), "r"(b), "r"(sel));
    return d;
}

// bf16 plane, 64 cols (128B rows), XOR-swizzled 16B chunks
__device__ __forceinline__ uint32_t boff(int row, int col) {  // col in bf16 units
    return (uint32_t)(row * 128 + ((col * 2) ^ ((row & 7) << 4)));
}
// u32 plane, 64 cols (256B rows), XOR-swizzled 32B chunks
__device__ __forceinline__ uint32_t uoff(int row, int col) {  // col in u32 units
    return (uint32_t)(row * 256 + ((col * 4) ^ ((row & 7) << 5)));
}

__device__ __forceinline__ void split1(float x, uint16_t& h, uint16_t& l) {
    __nv_bfloat16 hh = __float2bfloat16(x);
    __nv_bfloat16 ll = __float2bfloat16(x - __bfloat162float(hh));
    h = __bfloat16_as_ushort(hh);
    l = __bfloat16_as_ushort(ll);
}
__device__ __forceinline__ void split2(float a, float b, uint32_t& hi, uint32_t& lo) {
    uint16_t ha, la, hb, lb;
    split1(a, ha, la);
    split1(b, hb, lb);
    hi = (uint32_t)ha | ((uint32_t)hb << 16);
    lo = (uint32_t)la | ((uint32_t)lb << 16);
}
__device__ __forceinline__ uint32_t packsplit(float x) {  // hi in low16, lo in high16
    uint16_t h, l;
    split1(x, h, l);
    return (uint32_t)h | ((uint32_t)l << 16);
}

// A-fragment ldmatrix address helper: 16x16 tile at rows rbase.., bf16 col cb..
__device__ __forceinline__ uint32_t a_addr(uint32_t plane, int rbase, int cb, int lane) {
    int row = rbase + (lane & 7) + ((lane & 8) ? 8 : 0);
    int col = cb + ((lane & 16) ? 8 : 0);
    return plane + boff(row, col);
}
// B-fragment ldmatrix.x2 address: 8 n-rows at nbase, bf16 col cb (k) and cb+8
__device__ __forceinline__ uint32_t b_addr(uint32_t plane, int nbase, int cb, int lane) {
    int l = lane & 15;
    int row = nbase + (l & 7);
    int col = cb + ((l & 8) ? 8 : 0);
    return plane + boff(row, col);
}

// ===========================================================================
// Kernel A: QKV projection via mma.sync.  Tile 64m x 128n, K=128 in 2 chunks.
// Writes bf16 hi/lo packed planes.  grid (2048, 3), 256 thr.
// ===========================================================================
__global__ __launch_bounds__(256) void proj_kernel(
    const float* __restrict__ src,
    const float* __restrict__ W0, const float* __restrict__ b0p,
    const float* __restrict__ W1, const float* __restrict__ b1p,
    const float* __restrict__ W2, const float* __restrict__ b2p)
{
    __shared__ __align__(16) unsigned char sm[49152];
    // planes: Shi[64][64]bf16 @0 (8K), Slo @8192, Wthi[128n][64k] @16384 (16K), Wtlo @32768
    unsigned char* smp = sm;
    const uint32_t sb = smem_u32(sm);
    constexpr int SHI = 0, SLO = 8192, WHI = 16384, WLO = 32768;

    const float *W, *bias;
    uint32_t *ohi, *olo;
    if (blockIdx.y == 0)      { W = W0; bias = b0p; ohi = g_qhi; olo = g_qlo; }
    else if (blockIdx.y == 1) { W = W1; bias = b1p; ohi = g_khi; olo = g_klo; }
    else                      { W = W2; bias = b2p; ohi = g_vhi; olo = g_vlo; }

    const int t = threadIdx.x, lane = t & 31, w = t >> 5;
    const int wm = w >> 1, wn = w & 1;
    const int m0 = blockIdx.x * 64;

    float acc[8][4];
#pragma unroll
    for (int i = 0; i < 8; i++)
#pragma unroll
        for (int j = 0; j < 4; j++) acc[i][j] = 0.f;

    for (int kc = 0; kc < 2; kc++) {
        const int kb = kc * 64;
        // ---- stage S chunk [64m][64k] -> hi/lo planes ----
        {
            const int row = t >> 2, c0 = (t & 3) * 16;
            const float* p = src + (size_t)(m0 + row) * Dc + kb + c0;
            float4 f0 = *(const float4*)(p);
            float4 f1 = *(const float4*)(p + 4);
            float4 f2 = *(const float4*)(p + 8);
            float4 f3 = *(const float4*)(p + 12);
            uint32_t h[8], l[8];
            split2(f0.x, f0.y, h[0], l[0]); split2(f0.z, f0.w, h[1], l[1]);
            split2(f1.x, f1.y, h[2], l[2]); split2(f1.z, f1.w, h[3], l[3]);
            split2(f2.x, f2.y, h[4], l[4]); split2(f2.z, f2.w, h[5], l[5]);
            split2(f3.x, f3.y, h[6], l[6]); split2(f3.z, f3.w, h[7], l[7]);
            *(uint4*)(smp + SHI + boff(row, c0))     = make_uint4(h[0], h[1], h[2], h[3]);
            *(uint4*)(smp + SHI + boff(row, c0 + 8)) = make_uint4(h[4], h[5], h[6], h[7]);
            *(uint4*)(smp + SLO + boff(row, c0))     = make_uint4(l[0], l[1], l[2], l[3]);
            *(uint4*)(smp + SLO + boff(row, c0 + 8)) = make_uint4(l[4], l[5], l[6], l[7]);
        }
        // ---- stage W chunk transposed -> Wt[n][k] hi/lo planes ----
        {
            const int kp = t & 31;          // k pair: k = 2*kp
            const int ns = (t >> 5) * 16;   // 16 n values
            const float* wr0 = W + (size_t)(kb + 2 * kp) * Dc + ns;
            const float* wr1 = wr0 + Dc;
#pragma unroll
            for (int i = 0; i < 16; i += 4) {
                float4 a4 = *(const float4*)(wr0 + i);
                float4 c4 = *(const float4*)(wr1 + i);
                float av[4] = {a4.x, a4.y, a4.z, a4.w};
                float cv[4] = {c4.x, c4.y, c4.z, c4.w};
#pragma unroll
                for (int j = 0; j < 4; j++) {
                    const int n = ns + i + j;
                    uint16_t ha, la, hb, lb;
                    split1(av[j], ha, la);
                    split1(cv[j], hb, lb);
                    const uint32_t off = boff(n, 2 * kp);
                    *(uint32_t*)(smp + WHI + off) = (uint32_t)ha | ((uint32_t)hb << 16);
                    *(uint32_t*)(smp + WLO + off) = (uint32_t)la | ((uint32_t)lb << 16);
                }
            }
        }
        __syncthreads();

        // ---- MMA: 4 k-steps, 8 n-tiles, 3 split terms ----
#pragma unroll
        for (int ks = 0; ks < 4; ks++) {
            uint32_t ahi[4], alo[4];
            ldm_x4(ahi, sb + (uint32_t)SHI + a_addr(0, wm * 16, ks * 16, lane));
            ldm_x4(alo, sb + (uint32_t)SLO + a_addr(0, wm * 16, ks * 16, lane));
#pragma unroll
            for (int nt = 0; nt < 8; nt++) {
                const int nb = wn * 64 + nt * 8;
                uint32_t bhi[2], blo[2];
                ldm_x2(bhi, sb + (uint32_t)WHI + b_addr(0, nb, ks * 16, lane));
                ldm_x2(blo, sb + (uint32_t)WLO + b_addr(0, nb, ks * 16, lane));
                mma_bf16(acc[nt], ahi, bhi);
                mma_bf16(acc[nt], alo, bhi);
                mma_bf16(acc[nt], ahi, blo);
            }
        }
        __syncthreads();
    }

    // ---- epilogue: + bias, split, pack, store u32 pairs ----
    const int r0 = m0 + wm * 16 + (lane >> 2);
#pragma unroll
    for (int nt = 0; nt < 8; nt++) {
        const int col = wn * 64 + nt * 8 + (lane & 3) * 2;
        const float bb0 = __ldg(bias + col), bb1 = __ldg(bias + col + 1);
        uint32_t h01, l01, h23, l23;
        split2(acc[nt][0] + bb0, acc[nt][1] + bb1, h01, l01);
        split2(acc[nt][2] + bb0, acc[nt][3] + bb1, h23, l23);
        const size_t w0i = (size_t)r0 * 64 + (col >> 1);
        const size_t w1i = (size_t)(r0 + 8) * 64 + (col >> 1);
        ohi[w0i] = h01; olo[w0i] = l01;
        ohi[w1i] = h23; olo[w1i] = l23;
    }
}

// ===========================================================================
// Kernel B: fused relu-attention on mma.sync.  Per (b,i): 64 j-rows per block.
//   stage1: sacc = K_j . Q_k^T (split 3-term), relu*scale -> P packed smem
//   stage2: ctx += P @ V_k (split 3-term, V transposed in smem)
// grid (4, 512), 256 thr.
// ===========================================================================
__global__ __launch_bounds__(256) void attn_kernel()
{
    __shared__ __align__(16) unsigned char sm[49152];
    unsigned char* smp = sm;
    const uint32_t sb = smem_u32(sm);
    constexpr int KHI = 0, KLO = 8192, QHI = 16384, QLO = 24576;  // region A (32K)
    constexpr int POF = 32768;                                     // P packed (16K)
    constexpr int VT  = 0;                                         // Vt packed (32K, aliases A)

    const int t = threadIdx.x, lane = t & 31, w = t >> 5;
    const int wm = w >> 1, wn = w & 1;
    const int bi = blockIdx.y;
    const int j0 = blockIdx.x * 64;
    const size_t rowbase = (size_t)bi * Nc;

    float ctx[8][4];
#pragma unroll
    for (int i = 0; i < 8; i++)
#pragma unroll
        for (int j = 0; j < 4; j++) ctx[i][j] = 0.f;

    for (int kt = 0; kt < 4; kt++) {
        const int k0 = kt * 64;
        float sacc[4][4];
#pragma unroll
        for (int i = 0; i < 4; i++)
#pragma unroll
            for (int j = 0; j < 4; j++) sacc[i][j] = 0.f;

        for (int dc = 0; dc < 2; dc++) {
            // ---- stage K chunk [64j][64d] and Q chunk [64q][64d] (hi/lo) ----
            {
                const int row = t >> 2, us = (t & 3) * 8;  // 8 u32 = 16 bf16
                const size_t kr = (rowbase + j0 + row) * 64 + dc * 32 + us;
                const size_t qr = (rowbase + k0 + row) * 64 + dc * 32 + us;
                uint4 x;
                x = *(const uint4*)(g_khi + kr);
                *(uint4*)(smp + KHI + boff(row, us * 2)) = x;
                x = *(const uint4*)(g_khi + kr + 4);
                *(uint4*)(smp + KHI + boff(row, us * 2 + 8)) = x;
                x = *(const uint4*)(g_klo + kr);
                *(uint4*)(smp + KLO + boff(row, us * 2)) = x;
                x = *(const uint4*)(g_klo + kr + 4);
                *(uint4*)(smp + KLO + boff(row, us * 2 + 8)) = x;
                x = *(const uint4*)(g_qhi + qr);
                *(uint4*)(smp + QHI + boff(row, us * 2)) = x;
                x = *(const uint4*)(g_qhi + qr + 4);
                *(uint4*)(smp + QHI + boff(row, us * 2 + 8)) = x;
                x = *(const uint4*)(g_qlo + qr);
                *(uint4*)(smp + QLO + boff(row, us * 2)) = x;
                x = *(const uint4*)(g_qlo + qr + 4);
                *(uint4*)(smp + QLO + boff(row, us * 2 + 8)) = x;
            }
            __syncthreads();
            // ---- stage1 MMA: scores 16j x 32q per warp ----
#pragma unroll
            for (int ks = 0; ks < 4; ks++) {
                uint32_t ahi[4], alo[4];
                ldm_x4(ahi, sb + (uint32_t)KHI + a_addr(0, wm * 16, ks * 16, lane));
                ldm_x4(alo, sb + (uint32_t)KLO + a_addr(0, wm * 16, ks * 16, lane));
#pragma unroll
                for (int nt = 0; nt < 4; nt++) {
                    const int nb = wn * 32 + nt * 8;
                    uint32_t bhi[2], blo[2];
                    ldm_x2(bhi, sb + (uint32_t)QHI + b_addr(0, nb, ks * 16, lane));
                    ldm_x2(blo, sb + (uint32_t)QLO + b_addr(0, nb, ks * 16, lane));
                    mma_bf16(sacc[nt], ahi, bhi);
                    mma_bf16(sacc[nt], alo, bhi);
                    mma_bf16(sacc[nt], ahi, blo);
                }
            }
            __syncthreads();
        }

        // ---- relu + scale + split -> P packed plane ----
        {
            const int pr0 = wm * 16 + (lane >> 2);
#pragma unroll
            for (int nt = 0; nt < 4; nt++) {
                const int pc = wn * 32 + nt * 8 + (lane & 3) * 2;
                const uint32_t p0 = packsplit(fmaxf(sacc[nt][0] * SCALE, 0.f));
                const uint32_t p1 = packsplit(fmaxf(sacc[nt][1] * SCALE, 0.f));
                const uint32_t p2 = packsplit(fmaxf(sacc[nt][2] * SCALE, 0.f));
                const uint32_t p3 = packsplit(fmaxf(sacc[nt][3] * SCALE, 0.f));
                *(uint2*)(smp + POF + uoff(pr0, pc))     = make_uint2(p0, p1);
                *(uint2*)(smp + POF + uoff(pr0 + 8, pc)) = make_uint2(p2, p3);
            }
        }
        __syncthreads();

        // ---- stage Vt [128d][64k] packed (transpose of V chunk) ----
        {
            const int k = t >> 2, ds = (t & 3) * 32;  // 32 d values (16 u32 words)
            const uint32_t* vh = g_vhi + (rowbase + k0 + k) * 64 + (ds >> 1);
            const uint32_t* vl = g_vlo + (rowbase + k0 + k) * 64 + (ds >> 1);
#pragma unroll
            for (int i = 0; i < 16; i += 4) {
                uint4 H = *(const uint4*)(vh + i);
                uint4 L = *(const uint4*)(vl + i);
                uint32_t Hs[4] = {H.x, H.y, H.z, H.w};
                uint32_t Ls[4] = {L.x, L.y, L.z, L.w};
#pragma unroll
                for (int j = 0; j < 4; j++) {
                    const int d = ds + 2 * (i + j);
                    *(uint32_t*)(smp + VT + uoff(d, k))     = prmt(Hs[j], Ls[j], 0x5410u);
                    *(uint32_t*)(smp + VT + uoff(d + 1, k)) = prmt(Hs[j], Ls[j], 0x7632u);
                }
            }
        }
        __syncthreads();

        // ---- stage2 MMA: ctx 16j x 64d per warp ----
#pragma unroll
        for (int ks = 0; ks < 4; ks++) {
            const int pr = wm * 16 + (lane >> 2);
            const int kp = ks * 16 + (lane & 3) * 2;
            uint32_t ahi[4], alo[4];
            {
                uint2 w0 = *(const uint2*)(smp + POF + uoff(pr, kp));
                uint2 w1 = *(const uint2*)(smp + POF + uoff(pr + 8, kp));
                uint2 w2 = *(const uint2*)(smp + POF + uoff(pr, kp + 8));
                uint2 w3 = *(const uint2*)(smp + POF + uoff(pr + 8, kp + 8));
                ahi[0] = prmt(w0.x, w0.y, 0x5410u); alo[0] = prmt(w0.x, w0.y, 0x7632u);
                ahi[1] = prmt(w1.x, w1.y, 0x5410u); alo[1] = prmt(w1.x, w1.y, 0x7632u);
                ahi[2] = prmt(w2.x, w2.y, 0x5410u); alo[2] = prmt(w2.x, w2.y, 0x7632u);
                ahi[3] = prmt(w3.x, w3.y, 0x5410u); alo[3] = prmt(w3.x, w3.y, 0x7632u);
            }
#pragma unroll
            for (int nt = 0; nt < 8; nt++) {
                const int d = wn * 64 + nt * 8 + (lane >> 2);
                uint2 wB0 = *(const uint2*)(smp + VT + uoff(d, kp));
                uint2 wB1 = *(const uint2*)(smp + VT + uoff(d, kp + 8));
                uint32_t bhi[2], blo[2];
                bhi[0] = prmt(wB0.x, wB0.y, 0x5410u); blo[0] = prmt(wB0.x, wB0.y, 0x7632u);
                bhi[1] = prmt(wB1.x, wB1.y, 0x5410u); blo[1] = prmt(wB1.x, wB1.y, 0x7632u);
                mma_bf16(ctx[nt], ahi, bhi);
                mma_bf16(ctx[nt], alo, bhi);
                mma_bf16(ctx[nt], ahi, blo);
            }
        }
        __syncthreads();  // before next kt overwrites region A
    }

    // ---- write ctx fp32 ----
    const size_t gr = (rowbase + j0 + wm * 16 + (lane >> 2)) * Dc;
#pragma unroll
    for (int nt = 0; nt < 8; nt++) {
        const int col = wn * 64 + nt * 8 + (lane & 3) * 2;
        *(float2*)(g_ctx + gr + col)            = make_float2(ctx[nt][0], ctx[nt][1]);
        *(float2*)(g_ctx + gr + 8 * Dc + col)   = make_float2(ctx[nt][2], ctx[nt][3]);
    }
}

// ===========================================================================
// Kernel C: out = LN( ctx @ Wo + bo + S ).  GEMM on mma.sync + fused LN.
// grid 2048, 256 thr.
// ===========================================================================
__global__ __launch_bounds__(256) void outln_kernel(
    const float* __restrict__ Sres,
    const float* __restrict__ Wo, const float* __restrict__ bo,
    const float* __restrict__ lng, const float* __restrict__ lnb,
    float* __restrict__ outp)
{
    __shared__ __align__(16) unsigned char sm[49152];
    unsigned char* smp = sm;
    const uint32_t sb = smem_u32(sm);
    constexpr int SHI = 0, SLO = 8192, WHI = 16384, WLO = 32768;

    const int t = threadIdx.x, lane = t & 31, w = t >> 5;
    const int wm = w >> 1, wn = w & 1;
    const int m0 = blockIdx.x * 64;

    float acc[8][4];
#pragma unroll
    for (int i = 0; i < 8; i++)
#pragma unroll
        for (int j = 0; j < 4; j++) acc[i][j] = 0.f;

    for (int kc = 0; kc < 2; kc++) {
        const int kb = kc * 64;
        {   // stage ctx chunk
            const int row = t >> 2, c0 = (t & 3) * 16;
            const float* p = g_ctx + (size_t)(m0 + row) * Dc + kb + c0;
            float4 f0 = *(const float4*)(p);
            float4 f1 = *(const float4*)(p + 4);
            float4 f2 = *(const float4*)(p + 8);
            float4 f3 = *(const float4*)(p + 12);
            uint32_t h[8], l[8];
            split2(f0.x, f0.y, h[0], l[0]); split2(f0.z, f0.w, h[1], l[1]);
            split2(f1.x, f1.y, h[2], l[2]); split2(f1.z, f1.w, h[3], l[3]);
            split2(f2.x, f2.y, h[4], l[4]); split2(f2.z, f2.w, h[5], l[5]);
            split2(f3.x, f3.y, h[6], l[6]); split2(f3.z, f3.w, h[7], l[7]);
            *(uint4*)(smp + SHI + boff(row, c0))     = make_uint4(h[0], h[1], h[2], h[3]);
            *(uint4*)(smp + SHI + boff(row, c0 + 8)) = make_uint4(h[4], h[5], h[6], h[7]);
            *(uint4*)(smp + SLO + boff(row, c0))     = make_uint4(l[0], l[1], l[2], l[3]);
            *(uint4*)(smp + SLO + boff(row, c0 + 8)) = make_uint4(l[4], l[5], l[6], l[7]);
        }
        {   // stage Wo chunk transposed
            const int kp = t & 31;
            const int ns = (t >> 5) * 16;
            const float* wr0 = Wo + (size_t)(kb + 2 * kp) * Dc + ns;
            const float* wr1 = wr0 + Dc;
#pragma unroll
            for (int i = 0; i < 16; i += 4) {
                float4 a4 = *(const float4*)(wr0 + i);
                float4 c4 = *(const float4*)(wr1 + i);
                float av[4] = {a4.x, a4.y, a4.z, a4.w};
                float cv[4] = {c4.x, c4.y, c4.z, c4.w};
#pragma unroll
                for (int j = 0; j < 4; j++) {
                    const int n = ns + i + j;
                    uint16_t ha, la, hb, lb;
                    split1(av[j], ha, la);
                    split1(cv[j], hb, lb);
                    const uint32_t off = boff(n, 2 * kp);
                    *(uint32_t*)(smp + WHI + off) = (uint32_t)ha | ((uint32_t)hb << 16);
                    *(uint32_t*)(smp + WLO + off) = (uint32_t)la | ((uint32_t)lb << 16);
                }
            }
        }
        __syncthreads();
#pragma unroll
        for (int ks = 0; ks < 4; ks++) {
            uint32_t ahi[4], alo[4];
            ldm_x4(ahi, sb + (uint32_t)SHI + a_addr(0, wm * 16, ks * 16, lane));
            ldm_x4(alo, sb + (uint32_t)SLO + a_addr(0, wm * 16, ks * 16, lane));
#pragma unroll
            for (int nt = 0; nt < 8; nt++) {
                const int nb = wn * 64 + nt * 8;
                uint32_t bhi[2], blo[2];
                ldm_x2(bhi, sb + (uint32_t)WHI + b_addr(0, nb, ks * 16, lane));
                ldm_x2(blo, sb + (uint32_t)WLO + b_addr(0, nb, ks * 16, lane));
                mma_bf16(acc[nt], ahi, bhi);
                mma_bf16(acc[nt], alo, bhi);
                mma_bf16(acc[nt], ahi, blo);
            }
        }
        __syncthreads();
    }

    // ---- epilogue: x = acc + bo + residual -> smem, then LayerNorm ----
    float* Xs = (float*)sm;  // [64][132] fp32 (33792 B, aliases GEMM planes; synced above)
    {
        const int r0l = wm * 16 + (lane >> 2);
#pragma unroll
        for (int nt = 0; nt < 8; nt++) {
            const int col = wn * 64 + nt * 8 + (lane & 3) * 2;
            float2 rs0 = *(const float2*)(Sres + (size_t)(m0 + r0l) * Dc + col);
            float2 rs1 = *(const float2*)(Sres + (size_t)(m0 + r0l + 8) * Dc + col);
            const float bb0 = __ldg(bo + col), bb1 = __ldg(bo + col + 1);
            Xs[r0l * 132 + col]           = acc[nt][0] + bb0 + rs0.x;
            Xs[r0l * 132 + col + 1]       = acc[nt][1] + bb1 + rs0.y;
            Xs[(r0l + 8) * 132 + col]     = acc[nt][2] + bb0 + rs1.x;
            Xs[(r0l + 8) * 132 + col + 1] = acc[nt][3] + bb1 + rs1.y;
        }
    }
    __syncthreads();

    const int row = t >> 2, part = (t & 3) * 32;
    float sum = 0.f, sq = 0.f;
#pragma unroll
    for (int c = 0; c < 32; c++) {
        const float x = Xs[row * 132 + part + c];
        sum += x;
        sq += x * x;
    }
    sum += __shfl_xor_sync(0xffffffffu, sum, 1);
    sq  += __shfl_xor_sync(0xffffffffu, sq, 1);
    sum += __shfl_xor_sync(0xffffffffu, sum, 2);
    sq  += __shfl_xor_sync(0xffffffffu, sq, 2);
    const float mean = sum * (1.f / 128.f);
    const float var  = sq * (1.f / 128.f) - mean * mean;
    const float inv  = rsqrtf(var + LNEPS);

    float* orow = outp + (size_t)(m0 + row) * Dc + part;
#pragma unroll
    for (int c = 0; c < 32; c += 4) {
        float4 o;
        o.x = (Xs[row * 132 + part + c + 0] - mean) * inv * __ldg(lng + part + c + 0) + __ldg(lnb + part + c + 0);
        o.y = (Xs[row * 132 + part + c + 1] - mean) * inv * __ldg(lng + part + c + 1) + __ldg(lnb + part + c + 1);
        o.z = (Xs[row * 132 + part + c + 2] - mean) * inv * __ldg(lng + part + c + 2) + __ldg(lnb + part + c + 2);
        o.w = (Xs[row * 132 + part + c + 3] - mean) * inv * __ldg(lng + part + c + 3) + __ldg(lnb + part + c + 3);
        *(float4*)(orow + c) = o;
    }
}

// ---------------------------------------------------------------------------
// Launch. Inputs: hidden_states, structure_matrix, Wq, bq, Wk, bk, Wv, bv,
// Wo, bo, ln_g, ln_b. hidden_states unused by reference.
// ---------------------------------------------------------------------------
extern "C" void kernel_launch(void* const* d_in, const int* in_sizes, int n_in,
                              void* d_out, int out_size)
{
    const float* S   = (const float*)d_in[1];
    const float* Wq  = (const float*)d_in[2];
    const float* bq  = (const float*)d_in[3];
    const float* Wk  = (const float*)d_in[4];
    const float* bk  = (const float*)d_in[5];
    const float* Wv  = (const float*)d_in[6];
    const float* bv  = (const float*)d_in[7];
    const float* Wo  = (const float*)d_in[8];
    const float* bo  = (const float*)d_in[9];
    const float* lng = (const float*)d_in[10];
    const float* lnb = (const float*)d_in[11];
    float* out = (float*)d_out;

    proj_kernel<<<dim3(MROWS / 64, 3), 256>>>(S, Wq, bq, Wk, bk, Wv, bv);
    attn_kernel<<<dim3(Nc / 64, Bc * Nc), 256>>>();
    outln_kernel<<<MROWS / 64, 256>>>(S, Wo, bo, lng, lnb, out);
}